// round 1
// baseline (speedup 1.0000x reference)
#include <cuda_runtime.h>
#include <cuda_bf16.h>
#include <math.h>

#define Bsz 1024
#define Kn  200
#define Dm  128
#define D2  256
#define G8  1024   // 8*D

// ---------------- scratch (device globals; no allocation allowed) ----------------
__device__ float g_scat[Bsz * D2];      // [sum_rel | sum_ent] per row
__device__ float g_qe[Bsz * Dm];        // query embeddings
__device__ float g_sup[Bsz * Dm];       // support (after tanh)
__device__ float g_hid[Bsz * D2];       // FFN hidden
__device__ float g_z[Bsz * Dm];         // pre-layernorm
__device__ float g_sg[Bsz * Dm];        // support_g
__device__ float g_sgn2[Bsz];           // ||support_g||^2 per row
__device__ float g_qWb[Bsz * G8];       // q@w_ih^T + b_ih + b_hh
__device__ float g_gates[Bsz * G8];
__device__ float g_scores[Bsz * Bsz];
__device__ float g_c[Bsz * D2];         // LSTM cell state
__device__ float g_hout[Bsz * Dm];
__device__ float g_hr[Bsz * D2];        // [h_out | r]

// ---------------- gather-sum kernel ----------------
// block b: s_cat[b][0:128] = sum_k emb[rel[b,k]], [128:256] = sum_k emb[ent[b,k]]
// also qe[b] = emb[query[b]]
__global__ void gather_sum_kernel(const int* __restrict__ rel,
                                  const int* __restrict__ ent,
                                  const int* __restrict__ query,
                                  const float* __restrict__ emb) {
    __shared__ int sidx[2 * Kn];
    int b = blockIdx.x;
    int d = threadIdx.x;  // 128 threads
    for (int i = d; i < Kn; i += Dm) sidx[i] = rel[b * Kn + i];
    for (int i = d; i < Kn; i += Dm) sidx[Kn + i] = ent[b * Kn + i];
    __syncthreads();
    float ar = 0.f, ae = 0.f;
    #pragma unroll 4
    for (int k = 0; k < Kn; k++) ar += emb[sidx[k] * Dm + d];
    #pragma unroll 4
    for (int k = 0; k < Kn; k++) ae += emb[sidx[Kn + k] * Dm + d];
    g_scat[b * D2 + d] = ar;
    g_scat[b * D2 + Dm + d] = ae;
    g_qe[b * Dm + d] = emb[query[b] * Dm + d];
}

// ---------------- tiled SGEMM: C[m,n] = epilogue( sum_k A[m,k]*B[n,k] ) ----------------
// A: MxK row-major, B: NxK row-major. Tiles 64x64, BK=16, 256 thr, 4x4 microtile.
// modes: 0 none; 1 tanh((acc+200*bias)/1024); 2 relu(acc+bias);
//        3 acc+bias+addC; 4 acc+bias+bias2; 5 acc+addC
__global__ void gemm_kernel(const float* __restrict__ A, const float* __restrict__ B,
                            float* __restrict__ C, int M, int N, int K, int mode,
                            const float* __restrict__ bias, const float* __restrict__ bias2,
                            const float* __restrict__ addC) {
    __shared__ float As[16][68];
    __shared__ float Bs[16][68];
    int tid = threadIdx.x;
    int tx = tid & 15, ty = tid >> 4;         // 16 x 16
    int bx = blockIdx.x, by = blockIdx.y;
    int m0 = by * 64 + ty * 4;
    int n0 = bx * 64 + tx * 4;
    int lr = tid >> 2;                        // 0..63
    int lk = (tid & 3) * 4;                   // 0,4,8,12
    const float* Ab = A + (size_t)(by * 64 + lr) * K;
    const float* Bb = B + (size_t)(bx * 64 + lr) * K;
    float acc[4][4] = {};
    for (int k0 = 0; k0 < K; k0 += 16) {
        float4 av = *(const float4*)(Ab + k0 + lk);
        float4 bv = *(const float4*)(Bb + k0 + lk);
        __syncthreads();
        As[lk + 0][lr] = av.x; As[lk + 1][lr] = av.y;
        As[lk + 2][lr] = av.z; As[lk + 3][lr] = av.w;
        Bs[lk + 0][lr] = bv.x; Bs[lk + 1][lr] = bv.y;
        Bs[lk + 2][lr] = bv.z; Bs[lk + 3][lr] = bv.w;
        __syncthreads();
        #pragma unroll
        for (int k = 0; k < 16; k++) {
            float4 a4 = *(const float4*)&As[k][ty * 4];
            float4 b4 = *(const float4*)&Bs[k][tx * 4];
            acc[0][0] += a4.x * b4.x; acc[0][1] += a4.x * b4.y;
            acc[0][2] += a4.x * b4.z; acc[0][3] += a4.x * b4.w;
            acc[1][0] += a4.y * b4.x; acc[1][1] += a4.y * b4.y;
            acc[1][2] += a4.y * b4.z; acc[1][3] += a4.y * b4.w;
            acc[2][0] += a4.z * b4.x; acc[2][1] += a4.z * b4.y;
            acc[2][2] += a4.z * b4.z; acc[2][3] += a4.z * b4.w;
            acc[3][0] += a4.w * b4.x; acc[3][1] += a4.w * b4.y;
            acc[3][2] += a4.w * b4.z; acc[3][3] += a4.w * b4.w;
        }
    }
    float bi[4] = {0.f, 0.f, 0.f, 0.f};
    if (mode == 1 || mode == 2 || mode == 3 || mode == 4) {
        #pragma unroll
        for (int j = 0; j < 4; j++) bi[j] = bias[n0 + j];
        if (mode == 4) {
            #pragma unroll
            for (int j = 0; j < 4; j++) bi[j] += bias2[n0 + j];
        }
    }
    #pragma unroll
    for (int i = 0; i < 4; i++) {
        int m = m0 + i;
        float v[4];
        #pragma unroll
        for (int j = 0; j < 4; j++) v[j] = acc[i][j];
        if (mode == 1) {
            #pragma unroll
            for (int j = 0; j < 4; j++)
                v[j] = tanhf((v[j] + 200.0f * bi[j]) * (1.0f / 1024.0f));
        } else if (mode == 2) {
            #pragma unroll
            for (int j = 0; j < 4; j++) v[j] = fmaxf(v[j] + bi[j], 0.0f);
        } else if (mode == 3) {
            float4 ac = *(const float4*)&addC[(size_t)m * N + n0];
            v[0] += bi[0] + ac.x; v[1] += bi[1] + ac.y;
            v[2] += bi[2] + ac.z; v[3] += bi[3] + ac.w;
        } else if (mode == 4) {
            #pragma unroll
            for (int j = 0; j < 4; j++) v[j] += bi[j];
        } else if (mode == 5) {
            float4 ac = *(const float4*)&addC[(size_t)m * N + n0];
            v[0] += ac.x; v[1] += ac.y; v[2] += ac.z; v[3] += ac.w;
        }
        *(float4*)&C[(size_t)m * N + n0] = make_float4(v[0], v[1], v[2], v[3]);
    }
}

// ---------------- block reduce (128 threads) ----------------
__device__ __forceinline__ float blockReduceSum128(float v, float* ssum) {
    #pragma unroll
    for (int o = 16; o; o >>= 1) v += __shfl_xor_sync(0xffffffffu, v, o);
    if ((threadIdx.x & 31) == 0) ssum[threadIdx.x >> 5] = v;
    __syncthreads();
    float r = ssum[0] + ssum[1] + ssum[2] + ssum[3];
    __syncthreads();
    return r;
}

// ---------------- layernorm (unbiased std, eps added to std) ----------------
__global__ void ln_kernel(const float* __restrict__ lna, const float* __restrict__ lnb) {
    __shared__ float ssum[4];
    int b = blockIdx.x, d = threadIdx.x;
    float z = g_z[b * Dm + d];
    float mu = blockReduceSum128(z, ssum) * (1.0f / 128.0f);
    float diff = z - mu;
    float var = blockReduceSum128(diff * diff, ssum) * (1.0f / 127.0f);
    float sg = diff / (sqrtf(var) + 1e-3f) * lna[d] + lnb[d];
    g_sg[b * Dm + d] = sg;
    float n2 = blockReduceSum128(sg * sg, ssum);
    if (d == 0) g_sgn2[b] = n2;
}

// ---------------- LSTM cell elementwise ----------------
__global__ void lstm_cell_kernel(const float* __restrict__ gates_in, int first) {
    int b = blockIdx.x, j = threadIdx.x;  // 256 threads
    const float* g = gates_in + (size_t)b * G8;
    float gi = g[j], gf = g[D2 + j], gg = g[2 * D2 + j], go = g[3 * D2 + j];
    float cp = first ? 0.0f : g_c[b * D2 + j];
    float si = 1.0f / (1.0f + __expf(-gi));
    float sf = 1.0f / (1.0f + __expf(-gf));
    float so = 1.0f / (1.0f + __expf(-go));
    float c = sf * cp + si * tanhf(gg);
    g_c[b * D2 + j] = c;
    float h = so * tanhf(c);
    if (j < Dm) {
        float ho = g_qe[b * Dm + j] + h;
        g_hout[b * Dm + j] = ho;
        g_hr[b * D2 + j] = ho;
    }
}

// ---------------- fused softmax + AV ----------------
// 128 blocks x 8 rows, 128 threads. Reads g_scores, g_sg; writes r into g_hr[:,128:].
__global__ void attn_av_kernel() {
    __shared__ float p[8][Bsz];      // 32 KB (normalized probs)
    __shared__ float sgt[16][Dm];    // 8 KB
    int tid = threadIdx.x;
    int warp = tid >> 5, lane = tid & 31;
    int row0 = blockIdx.x * 8;
    // phase 1: softmax (warp w handles rows 2w, 2w+1)
    for (int rr = 0; rr < 2; rr++) {
        int i = warp * 2 + rr;
        const float* srow = g_scores + (size_t)(row0 + i) * Bsz;
        float v[32];
        float m = -1e30f;
        #pragma unroll
        for (int t = 0; t < 32; t++) { v[t] = srow[lane + t * 32]; m = fmaxf(m, v[t]); }
        #pragma unroll
        for (int o = 16; o; o >>= 1) m = fmaxf(m, __shfl_xor_sync(0xffffffffu, m, o));
        float l = 0.f;
        #pragma unroll
        for (int t = 0; t < 32; t++) { float e = __expf(v[t] - m); p[i][lane + t * 32] = e; l += e; }
        #pragma unroll
        for (int o = 16; o; o >>= 1) l += __shfl_xor_sync(0xffffffffu, l, o);
        float inv = 1.0f / l;
        #pragma unroll
        for (int t = 0; t < 32; t++) p[i][lane + t * 32] *= inv;
    }
    __syncthreads();
    // phase 2: r = p @ support_g  (microtile: 2 rows x 4 dims per thread)
    int rg = warp;           // 4 groups x 2 rows
    int d0 = (tid & 31) * 4; // 4 dims
    float a00 = 0, a01 = 0, a02 = 0, a03 = 0;
    float a10 = 0, a11 = 0, a12 = 0, a13 = 0;
    for (int jt = 0; jt < Bsz; jt += 16) {
        __syncthreads();
        for (int idx = tid; idx < 512; idx += 128) {
            int jj = idx >> 5;
            int dd = (idx & 31) * 4;
            *(float4*)&sgt[jj][dd] = *(const float4*)&g_sg[(size_t)(jt + jj) * Dm + dd];
        }
        __syncthreads();
        #pragma unroll
        for (int j = 0; j < 16; j++) {
            float4 sv = *(const float4*)&sgt[j][d0];
            float p0 = p[rg * 2][jt + j];
            float p1 = p[rg * 2 + 1][jt + j];
            a00 += p0 * sv.x; a01 += p0 * sv.y; a02 += p0 * sv.z; a03 += p0 * sv.w;
            a10 += p1 * sv.x; a11 += p1 * sv.y; a12 += p1 * sv.z; a13 += p1 * sv.w;
        }
    }
    int b0 = row0 + rg * 2;
    *(float4*)&g_hr[(size_t)b0 * D2 + Dm + d0] = make_float4(a00, a01, a02, a03);
    *(float4*)&g_hr[(size_t)(b0 + 1) * D2 + Dm + d0] = make_float4(a10, a11, a12, a13);
}

// ---------------- final cosine ----------------
__global__ void cosine_kernel(float* __restrict__ out) {
    __shared__ float ssum[4];
    int b = blockIdx.x, d = threadIdx.x;
    float ho = g_hout[b * Dm + d];
    float sg = g_sg[b * Dm + d];
    float cross = blockReduceSum128(ho * sg, ssum);
    float n1 = blockReduceSum128(ho * ho, ssum);
    if (d == 0) out[b] = cross * rsqrtf(n1 * g_sgn2[b]);
}

// ---------------- host orchestration ----------------
extern "C" void kernel_launch(void* const* d_in, const int* in_sizes, int n_in,
                              void* d_out, int out_size) {
    (void)in_sizes; (void)n_in; (void)out_size;
    const int*   relations = (const int*)d_in[0];
    const int*   entities  = (const int*)d_in[1];
    const int*   query     = (const int*)d_in[2];
    const float* emb       = (const float*)d_in[3];
    const float* gcn_w     = (const float*)d_in[4];
    const float* gcn_b     = (const float*)d_in[5];
    const float* p1_w      = (const float*)d_in[6];
    const float* p1_b      = (const float*)d_in[7];
    const float* p2_w      = (const float*)d_in[8];
    const float* p2_b      = (const float*)d_in[9];
    const float* ln_a      = (const float*)d_in[10];
    const float* ln_b      = (const float*)d_in[11];
    const float* w_ih      = (const float*)d_in[12];
    const float* w_hh      = (const float*)d_in[13];
    const float* b_ih      = (const float*)d_in[14];
    const float* b_hh      = (const float*)d_in[15];
    float* out = (float*)d_out;

    float *scat, *qe, *sup, *hid, *z, *sg, *qWb, *gates, *scores, *hout, *hr;
    cudaGetSymbolAddress((void**)&scat,   g_scat);
    cudaGetSymbolAddress((void**)&qe,     g_qe);
    cudaGetSymbolAddress((void**)&sup,    g_sup);
    cudaGetSymbolAddress((void**)&hid,    g_hid);
    cudaGetSymbolAddress((void**)&z,      g_z);
    cudaGetSymbolAddress((void**)&sg,     g_sg);
    cudaGetSymbolAddress((void**)&qWb,    g_qWb);
    cudaGetSymbolAddress((void**)&gates,  g_gates);
    cudaGetSymbolAddress((void**)&scores, g_scores);
    cudaGetSymbolAddress((void**)&hout,   g_hout);
    cudaGetSymbolAddress((void**)&hr,     g_hr);

    // 1) gather + sum over neighbors, plus query gather
    gather_sum_kernel<<<Bsz, Dm>>>(relations, entities, query, emb);

    // 2) support = tanh((scat @ gcn_w^T + 200*b) / 1024)
    gemm_kernel<<<dim3(Dm / 64, Bsz / 64), 256>>>(scat, gcn_w, sup, Bsz, Dm, D2, 1,
                                                  gcn_b, nullptr, nullptr);
    // 3) hidden = relu(support @ p1_w^T + p1_b)
    gemm_kernel<<<dim3(D2 / 64, Bsz / 64), 256>>>(sup, p1_w, hid, Bsz, D2, Dm, 2,
                                                  p1_b, nullptr, nullptr);
    // 4) z = hidden @ p2_w^T + p2_b + support
    gemm_kernel<<<dim3(Dm / 64, Bsz / 64), 256>>>(hid, p2_w, z, Bsz, Dm, D2, 3,
                                                  p2_b, nullptr, sup);
    // 5) support_g = layernorm(z); also ||support_g||^2
    ln_kernel<<<Bsz, Dm>>>(ln_a, ln_b);

    // 6) loop-invariant: qWb = qe @ w_ih^T + b_ih + b_hh
    gemm_kernel<<<dim3(G8 / 64, Bsz / 64), 256>>>(qe, w_ih, qWb, Bsz, G8, Dm, 4,
                                                  b_ih, b_hh, nullptr);

    // 7) step 1: h_r = 0 -> gates = qWb
    lstm_cell_kernel<<<Bsz, D2>>>(qWb, 1);

    // 8) steps 2..4: attention -> gates -> cell  (last attention is dead, skipped)
    for (int s = 1; s < 4; s++) {
        gemm_kernel<<<dim3(Bsz / 64, Bsz / 64), 256>>>(hout, sg, scores, Bsz, Bsz, Dm, 0,
                                                       nullptr, nullptr, nullptr);
        attn_av_kernel<<<Bsz / 8, 128>>>();
        gemm_kernel<<<dim3(G8 / 64, Bsz / 64), 256>>>(hr, w_hh, gates, Bsz, G8, D2, 5,
                                                      nullptr, nullptr, qWb);
        lstm_cell_kernel<<<Bsz, D2>>>(gates, 0);
    }

    // 9) cosine similarity
    cosine_kernel<<<Bsz, Dm>>>(out);
}

// round 3
// speedup vs baseline: 1.3665x; 1.3665x over previous
#include <cuda_runtime.h>
#include <cuda_bf16.h>
#include <math.h>
#include <cstdint>

#define Bsz 1024
#define Kn  200
#define Dm  128
#define D2  256
#define G8  1024

typedef __nv_bfloat16 bf16;

__device__ __forceinline__ void split2(float x, bf16& h, bf16& l) {
    h = __float2bfloat16(x);
    l = __float2bfloat16(x - __bfloat162float(h));
}

__device__ __forceinline__ void mma16816(float* c, const uint32_t* a, const uint32_t* b) {
    asm volatile(
        "mma.sync.aligned.m16n8k16.row.col.f32.bf16.bf16.f32 "
        "{%0,%1,%2,%3}, {%4,%5,%6,%7}, {%8,%9}, {%0,%1,%2,%3};"
        : "+f"(c[0]), "+f"(c[1]), "+f"(c[2]), "+f"(c[3])
        : "r"(a[0]), "r"(a[1]), "r"(a[2]), "r"(a[3]), "r"(b[0]), "r"(b[1]));
}

// ================= scratch =================
__device__ float g_qe[Bsz * Dm];
__device__ float g_sup[Bsz * Dm];
__device__ float g_hid[Bsz * D2];
__device__ float g_z[Bsz * Dm];
__device__ float g_sg[Bsz * Dm];
__device__ float g_sgn2[Bsz];
__device__ float g_qWb[Bsz * G8];
__device__ float g_gates[Bsz * G8];
__device__ float g_scores[Bsz * Bsz];
__device__ float g_c[Bsz * D2];
__device__ float g_hout[Bsz * Dm];
__device__ float g_rp[8 * Bsz * Dm];

__device__ bf16 g_scatA[Bsz * 768];
__device__ bf16 g_qeA[Bsz * 384];
__device__ bf16 g_supA[Bsz * 384];
__device__ bf16 g_hidA[Bsz * 768];
__device__ bf16 g_houtA[Bsz * 384];
__device__ bf16 g_hrA[Bsz * 768];
__device__ bf16 g_P[Bsz * 3072];
__device__ bf16 g_sgB[Bsz * 384];     // B for scores: [h|l|h] over K=128
__device__ bf16 g_sgT[Dm * 3072];     // B for AV: per-128-group [h|l|h]
__device__ bf16 g_gcnB[Dm * 768];
__device__ bf16 g_p1B[D2 * 384];
__device__ bf16 g_p2B[Dm * 768];
__device__ bf16 g_wihB[G8 * 384];
__device__ bf16 g_whhB[G8 * 768];

// ================= operand conversion =================
// A-side: [hi | hi | lo], B-side: [hi | lo | hi]; product of K-folded splits gives
// ah*bh + ah*bl + al*bh  (drops only the ~2^-16 al*bl term).
__global__ void convA_kernel(const float* __restrict__ src, bf16* __restrict__ dst, int K) {
    int m = blockIdx.x, j = threadIdx.x;
    bf16 h, l; split2(src[(size_t)m * K + j], h, l);
    bf16* d = dst + (size_t)m * 3 * K;
    d[j] = h; d[K + j] = h; d[2 * K + j] = l;
}
__global__ void convB_kernel(const float* __restrict__ src, bf16* __restrict__ dst, int K) {
    int n = blockIdx.x, j = threadIdx.x;
    bf16 h, l; split2(src[(size_t)n * K + j], h, l);
    bf16* d = dst + (size_t)n * 3 * K;
    d[j] = h; d[K + j] = l; d[2 * K + j] = h;
}

// ================= gather-sum =================
__global__ void gather_sum_kernel(const int* __restrict__ rel,
                                  const int* __restrict__ ent,
                                  const int* __restrict__ query,
                                  const float* __restrict__ emb) {
    __shared__ int sidx[2 * Kn];
    int b = blockIdx.x, d = threadIdx.x;
    for (int i = d; i < Kn; i += Dm) sidx[i] = rel[b * Kn + i];
    for (int i = d; i < Kn; i += Dm) sidx[Kn + i] = ent[b * Kn + i];
    __syncthreads();
    float ar = 0.f, ae = 0.f;
    #pragma unroll 8
    for (int k = 0; k < Kn; k++) ar += __ldg(&emb[(size_t)sidx[k] * Dm + d]);
    #pragma unroll 8
    for (int k = 0; k < Kn; k++) ae += __ldg(&emb[(size_t)sidx[Kn + k] * Dm + d]);
    bf16 h, l;
    bf16* sa = g_scatA + (size_t)b * 768;      // K=256, layout [h|h|l]
    split2(ar, h, l); sa[d] = h; sa[256 + d] = h; sa[512 + d] = l;
    split2(ae, h, l); sa[128 + d] = h; sa[384 + d] = h; sa[640 + d] = l;
    float qv = emb[(size_t)query[b] * Dm + d];
    g_qe[b * Dm + d] = qv;
    bf16* qa = g_qeA + (size_t)b * 384;
    split2(qv, h, l); qa[d] = h; qa[128 + d] = h; qa[256 + d] = l;
}

// ================= bf16 mma.sync GEMM =================
// C[M,N](+epilogue) = A[M,K3] . B[N,K3]^T. CTA tile 128x128, BK=64, 8 warps 4x2,
// warp tile 32x64. grid=(N/128, M/128, KS); split-K: koff=z*klen, C += z*M*N.
// modes: 0 store; 1 tanh((v+200*b)/1024); 2 relu(v+b); 3 v+b+addC; 4 v+b+b2; 5 v+addC
#define SMS 88
__global__ __launch_bounds__(256, 1)
void gemm_mma(const bf16* __restrict__ A, const bf16* __restrict__ B,
              float* __restrict__ C, int M, int N, int K3, int klen, int mode,
              const float* __restrict__ bias, const float* __restrict__ bias2,
              const float* __restrict__ addC) {
    __shared__ bf16 Asm[128][SMS];
    __shared__ bf16 Bsm[128][SMS];
    int tid = threadIdx.x;
    int wid = tid >> 5, lane = tid & 31;
    int g = lane >> 2, t = lane & 3;
    int wm = wid & 3, wn = wid >> 2;
    int nblk = blockIdx.x, mblk = blockIdx.y;
    int koff = blockIdx.z * klen;
    const bf16* Ab = A + (size_t)(mblk * 128) * K3 + koff;
    const bf16* Bb = B + (size_t)(nblk * 128) * K3 + koff;

    float acc[2][8][4];
    #pragma unroll
    for (int i = 0; i < 2; i++)
        #pragma unroll
        for (int j = 0; j < 8; j++)
            #pragma unroll
            for (int q = 0; q < 4; q++) acc[i][j][q] = 0.f;

    int ldr = tid >> 3;            // 0..31 (row block of 4 per iter)
    int ldc = (tid & 7) * 8;       // 0..56
    int nch = klen >> 6;
    for (int c = 0; c < nch; c++) {
        __syncthreads();
        #pragma unroll
        for (int i = 0; i < 4; i++) {
            int row = ldr + i * 32;
            uint4 va = *(const uint4*)(Ab + (size_t)row * K3 + c * 64 + ldc);
            uint4 vb = *(const uint4*)(Bb + (size_t)row * K3 + c * 64 + ldc);
            *(uint4*)&Asm[row][ldc] = va;
            *(uint4*)&Bsm[row][ldc] = vb;
        }
        __syncthreads();
        #pragma unroll
        for (int k = 0; k < 4; k++) {
            uint32_t a[2][4], b[8][2];
            #pragma unroll
            for (int im = 0; im < 2; im++) {
                int r = wm * 32 + im * 16 + g;
                a[im][0] = *(const uint32_t*)&Asm[r][k * 16 + 2 * t];
                a[im][1] = *(const uint32_t*)&Asm[r + 8][k * 16 + 2 * t];
                a[im][2] = *(const uint32_t*)&Asm[r][k * 16 + 2 * t + 8];
                a[im][3] = *(const uint32_t*)&Asm[r + 8][k * 16 + 2 * t + 8];
            }
            #pragma unroll
            for (int jn = 0; jn < 8; jn++) {
                int n = wn * 64 + jn * 8 + g;
                b[jn][0] = *(const uint32_t*)&Bsm[n][k * 16 + 2 * t];
                b[jn][1] = *(const uint32_t*)&Bsm[n][k * 16 + 2 * t + 8];
            }
            #pragma unroll
            for (int im = 0; im < 2; im++)
                #pragma unroll
                for (int jn = 0; jn < 8; jn++)
                    mma16816(acc[im][jn], a[im], b[jn]);
        }
    }

    float* Cz = C + (size_t)blockIdx.z * M * N;
    #pragma unroll
    for (int im = 0; im < 2; im++) {
        #pragma unroll
        for (int jn = 0; jn < 8; jn++) {
            int r0 = mblk * 128 + wm * 32 + im * 16 + g;
            int cb = nblk * 128 + wn * 64 + jn * 8 + 2 * t;
            float v0 = acc[im][jn][0], v1 = acc[im][jn][1];
            float v2 = acc[im][jn][2], v3 = acc[im][jn][3];
            if (mode == 1) {
                float b0 = 200.0f * __ldg(&bias[cb]), b1 = 200.0f * __ldg(&bias[cb + 1]);
                v0 = tanhf((v0 + b0) * (1.0f / 1024.0f));
                v1 = tanhf((v1 + b1) * (1.0f / 1024.0f));
                v2 = tanhf((v2 + b0) * (1.0f / 1024.0f));
                v3 = tanhf((v3 + b1) * (1.0f / 1024.0f));
            } else if (mode == 2) {
                float b0 = __ldg(&bias[cb]), b1 = __ldg(&bias[cb + 1]);
                v0 = fmaxf(v0 + b0, 0.f); v1 = fmaxf(v1 + b1, 0.f);
                v2 = fmaxf(v2 + b0, 0.f); v3 = fmaxf(v3 + b1, 0.f);
            } else if (mode == 3) {
                float b0 = __ldg(&bias[cb]), b1 = __ldg(&bias[cb + 1]);
                float2 a0 = *(const float2*)&addC[(size_t)r0 * N + cb];
                float2 a1 = *(const float2*)&addC[(size_t)(r0 + 8) * N + cb];
                v0 += b0 + a0.x; v1 += b1 + a0.y;
                v2 += b0 + a1.x; v3 += b1 + a1.y;
            } else if (mode == 4) {
                float b0 = __ldg(&bias[cb]) + __ldg(&bias2[cb]);
                float b1 = __ldg(&bias[cb + 1]) + __ldg(&bias2[cb + 1]);
                v0 += b0; v1 += b1; v2 += b0; v3 += b1;
            } else if (mode == 5) {
                float2 a0 = *(const float2*)&addC[(size_t)r0 * N + cb];
                float2 a1 = *(const float2*)&addC[(size_t)(r0 + 8) * N + cb];
                v0 += a0.x; v1 += a0.y; v2 += a1.x; v3 += a1.y;
            }
            *(float2*)&Cz[(size_t)r0 * N + cb] = make_float2(v0, v1);
            *(float2*)&Cz[(size_t)(r0 + 8) * N + cb] = make_float2(v2, v3);
        }
    }
}

// ================= reductions / elementwise =================
__device__ __forceinline__ float bred128(float v, float* s) {
    #pragma unroll
    for (int o = 16; o; o >>= 1) v += __shfl_xor_sync(0xffffffffu, v, o);
    if ((threadIdx.x & 31) == 0) s[threadIdx.x >> 5] = v;
    __syncthreads();
    float r = s[0] + s[1] + s[2] + s[3];
    __syncthreads();
    return r;
}

__global__ void ln_kernel(const float* __restrict__ lna, const float* __restrict__ lnb) {
    __shared__ float s[4];
    int b = blockIdx.x, d = threadIdx.x;
    float z = g_z[b * Dm + d];
    float mu = bred128(z, s) * (1.0f / 128.0f);
    float diff = z - mu;
    float var = bred128(diff * diff, s) * (1.0f / 127.0f);
    float sg = diff / (sqrtf(var) + 1e-3f) * lna[d] + lnb[d];
    g_sg[b * Dm + d] = sg;
    float n2 = bred128(sg * sg, s);
    if (d == 0) g_sgn2[b] = n2;
    bf16 h, l; split2(sg, h, l);
    bf16* sb = g_sgB + (size_t)b * 384;                 // scores B: [h|l|h]
    sb[d] = h; sb[128 + d] = l; sb[256 + d] = h;
    size_t tb = (size_t)d * 3072 + (b >> 7) * 384 + (b & 127);   // AV B
    g_sgT[tb] = h; g_sgT[tb + 128] = l; g_sgT[tb + 256] = h;
}

__global__ void lstm_cell_kernel(const float* __restrict__ gates_in, int first) {
    int b = blockIdx.x, j = threadIdx.x;  // 256 threads
    const float* g = gates_in + (size_t)b * G8;
    float gi = g[j], gf = g[D2 + j], gg = g[2 * D2 + j], go = g[3 * D2 + j];
    float cp = first ? 0.0f : g_c[b * D2 + j];
    float si = 1.0f / (1.0f + __expf(-gi));
    float sf = 1.0f / (1.0f + __expf(-gf));
    float so = 1.0f / (1.0f + __expf(-go));
    float c = sf * cp + si * tanhf(gg);
    g_c[b * D2 + j] = c;
    float h = so * tanhf(c);
    if (j < Dm) {
        float ho = g_qe[b * Dm + j] + h;
        g_hout[b * Dm + j] = ho;
        bf16 hh, ll; split2(ho, hh, ll);
        bf16* ha = g_houtA + (size_t)b * 384;
        ha[j] = hh; ha[128 + j] = hh; ha[256 + j] = ll;
        bf16* ra = g_hrA + (size_t)b * 768;   // h_r = [h_out | r], K=256, [h|h|l]
        ra[j] = hh; ra[256 + j] = hh; ra[512 + j] = ll;
    }
}

__global__ void softmax_kernel() {
    __shared__ float s[8];
    int b = blockIdx.x, t = threadIdx.x;  // 256 threads, 4 elems each
    const float4* row = (const float4*)(g_scores + (size_t)b * Bsz);
    float4 x = row[t];
    float m = fmaxf(fmaxf(x.x, x.y), fmaxf(x.z, x.w));
    #pragma unroll
    for (int o = 16; o; o >>= 1) m = fmaxf(m, __shfl_xor_sync(0xffffffffu, m, o));
    if ((t & 31) == 0) s[t >> 5] = m;
    __syncthreads();
    m = fmaxf(fmaxf(fmaxf(s[0], s[1]), fmaxf(s[2], s[3])),
              fmaxf(fmaxf(s[4], s[5]), fmaxf(s[6], s[7])));
    __syncthreads();
    float e0 = __expf(x.x - m), e1 = __expf(x.y - m);
    float e2 = __expf(x.z - m), e3 = __expf(x.w - m);
    float l = e0 + e1 + e2 + e3;
    #pragma unroll
    for (int o = 16; o; o >>= 1) l += __shfl_xor_sync(0xffffffffu, l, o);
    if ((t & 31) == 0) s[t >> 5] = l;
    __syncthreads();
    l = s[0] + s[1] + s[2] + s[3] + s[4] + s[5] + s[6] + s[7];
    float inv = 1.0f / l;
    float p[4] = {e0 * inv, e1 * inv, e2 * inv, e3 * inv};
    int j0 = t * 4;
    int ks = j0 >> 7, jl0 = j0 & 127;
    bf16* base = g_P + (size_t)b * 3072 + ks * 384 + jl0;
    #pragma unroll
    for (int q = 0; q < 4; q++) {
        bf16 h, lo; split2(p[q], h, lo);
        base[q] = h; base[128 + q] = h; base[256 + q] = lo;
    }
}

__global__ void reduce_r_kernel() {
    int b = blockIdx.x, d = threadIdx.x;  // 128 threads
    float r = 0.f;
    #pragma unroll
    for (int z = 0; z < 8; z++) r += g_rp[(size_t)z * Bsz * Dm + b * Dm + d];
    bf16 h, l; split2(r, h, l);
    bf16* ra = g_hrA + (size_t)b * 768;
    ra[128 + d] = h; ra[384 + d] = h; ra[640 + d] = l;
}

__global__ void cosine_kernel(float* __restrict__ out) {
    __shared__ float s[4];
    int b = blockIdx.x, d = threadIdx.x;
    float ho = g_hout[b * Dm + d];
    float sg = g_sg[b * Dm + d];
    float cross = bred128(ho * sg, s);
    float n1 = bred128(ho * ho, s);
    if (d == 0) out[b] = cross * rsqrtf(n1 * g_sgn2[b]);
}

// ================= host orchestration =================
extern "C" void kernel_launch(void* const* d_in, const int* in_sizes, int n_in,
                              void* d_out, int out_size) {
    (void)in_sizes; (void)n_in; (void)out_size;
    const int*   relations = (const int*)d_in[0];
    const int*   entities  = (const int*)d_in[1];
    const int*   query     = (const int*)d_in[2];
    const float* emb       = (const float*)d_in[3];
    const float* gcn_w     = (const float*)d_in[4];
    const float* gcn_b     = (const float*)d_in[5];
    const float* p1_w      = (const float*)d_in[6];
    const float* p1_b      = (const float*)d_in[7];
    const float* p2_w      = (const float*)d_in[8];
    const float* p2_b      = (const float*)d_in[9];
    const float* ln_a      = (const float*)d_in[10];
    const float* ln_b      = (const float*)d_in[11];
    const float* w_ih      = (const float*)d_in[12];
    const float* w_hh      = (const float*)d_in[13];
    const float* b_ih      = (const float*)d_in[14];
    const float* b_hh      = (const float*)d_in[15];
    float* out = (float*)d_out;

    float *sup, *hid, *z, *qWb, *gates, *scores, *rp;
    bf16 *scatA, *qeA, *supA, *hidA, *houtA, *hrA, *P, *sgB, *sgT;
    bf16 *gcnB, *p1B, *p2B, *wihB, *whhB;
    cudaGetSymbolAddress((void**)&sup, g_sup);
    cudaGetSymbolAddress((void**)&hid, g_hid);
    cudaGetSymbolAddress((void**)&z, g_z);
    cudaGetSymbolAddress((void**)&qWb, g_qWb);
    cudaGetSymbolAddress((void**)&gates, g_gates);
    cudaGetSymbolAddress((void**)&scores, g_scores);
    cudaGetSymbolAddress((void**)&rp, g_rp);
    cudaGetSymbolAddress((void**)&scatA, g_scatA);
    cudaGetSymbolAddress((void**)&qeA, g_qeA);
    cudaGetSymbolAddress((void**)&supA, g_supA);
    cudaGetSymbolAddress((void**)&hidA, g_hidA);
    cudaGetSymbolAddress((void**)&houtA, g_houtA);
    cudaGetSymbolAddress((void**)&hrA, g_hrA);
    cudaGetSymbolAddress((void**)&P, g_P);
    cudaGetSymbolAddress((void**)&sgB, g_sgB);
    cudaGetSymbolAddress((void**)&sgT, g_sgT);
    cudaGetSymbolAddress((void**)&gcnB, g_gcnB);
    cudaGetSymbolAddress((void**)&p1B, g_p1B);
    cudaGetSymbolAddress((void**)&p2B, g_p2B);
    cudaGetSymbolAddress((void**)&wihB, g_wihB);
    cudaGetSymbolAddress((void**)&whhB, g_whhB);

    // weight conversions (B-side [h|l|h])
    convB_kernel<<<Dm, D2>>>(gcn_w, gcnB, D2);
    convB_kernel<<<D2, Dm>>>(p1_w, p1B, Dm);
    convB_kernel<<<Dm, D2>>>(p2_w, p2B, D2);
    convB_kernel<<<G8, Dm>>>(w_ih, wihB, Dm);
    convB_kernel<<<G8, D2>>>(w_hh, whhB, D2);

    // gather + neighbor sums (writes scatA, qe, qeA)
    gather_sum_kernel<<<Bsz, Dm>>>(relations, entities, query, emb);

    // sup = tanh((scat.gcn_w^T + 200 b)/1024)
    gemm_mma<<<dim3(1, 8, 1), 256>>>(scatA, gcnB, sup, Bsz, Dm, 768, 768, 1,
                                     gcn_b, nullptr, nullptr);
    convA_kernel<<<Bsz, Dm>>>(sup, supA, Dm);
    // hid = relu(sup.p1_w^T + p1_b)
    gemm_mma<<<dim3(2, 8, 1), 256>>>(supA, p1B, hid, Bsz, D2, 384, 384, 2,
                                     p1_b, nullptr, nullptr);
    convA_kernel<<<Bsz, D2>>>(hid, hidA, D2);
    // z = hid.p2_w^T + p2_b + sup
    gemm_mma<<<dim3(1, 8, 1), 256>>>(hidA, p2B, z, Bsz, Dm, 768, 768, 3,
                                     p2_b, nullptr, sup);
    // support_g + attention operand splits
    ln_kernel<<<Bsz, Dm>>>(ln_a, ln_b);
    // qWb = qe.w_ih^T + b_ih + b_hh  (loop-invariant)
    gemm_mma<<<dim3(8, 8, 1), 256>>>(qeA, wihB, qWb, Bsz, G8, 384, 384, 4,
                                     b_ih, b_hh, nullptr);
    // step 1 (h_r = 0 -> gates = qWb)
    lstm_cell_kernel<<<Bsz, D2>>>(qWb, 1);

    for (int s = 1; s < 4; s++) {
        // scores = h_out . sg^T
        gemm_mma<<<dim3(8, 8, 1), 256>>>(houtA, sgB, scores, Bsz, Bsz, 384, 384, 0,
                                         nullptr, nullptr, nullptr);
        softmax_kernel<<<Bsz, 256>>>();
        // r partials = P . sgT^T (split-K over z, 8 slices of 384)
        gemm_mma<<<dim3(1, 8, 8), 256>>>(P, sgT, rp, Bsz, Dm, 3072, 384, 0,
                                         nullptr, nullptr, nullptr);
        reduce_r_kernel<<<Bsz, Dm>>>();
        // gates = h_r . w_hh^T + qWb
        gemm_mma<<<dim3(8, 8, 1), 256>>>(hrA, whhB, gates, Bsz, G8, 768, 768, 5,
                                         nullptr, nullptr, qWb);
        lstm_cell_kernel<<<Bsz, D2>>>(gates, 0);
    }
    cosine_kernel<<<Bsz, Dm>>>(out);
}